// round 8
// baseline (speedup 1.0000x reference)
#include <cuda_runtime.h>
#include <math_constants.h>

// GCN_20753281975108: top-k masked neighbor aggregation.
// N=50000 nodes, M=32 mailbox, D=128 features, K=8 top-k.
// Output (f32): [ aggregate: N*D ][ selected_ids: N*K cast to f32 ]
//
// One node per warp (occ ~90%, regs 32, grid 6250). ALL global traffic
// is read-once/write-once -> streaming cache policy (__ldcs/__stcs) on
// every access so nothing allocates in L1/L2.

#define M_MB   32
#define D_FEAT 128
#define K_TOP  8

__global__ __launch_bounds__(256, 8)
void gcn_kernel(const float* __restrict__ interact,
                const float* __restrict__ initial,
                const float* __restrict__ src_info,
                const float* __restrict__ buffer,
                const float* __restrict__ keep_rate_p,
                const int* __restrict__ source_id,
                float* __restrict__ out_agg,
                float* __restrict__ out_ids,
                int n_nodes)
{
    const int warp_global = (blockIdx.x * blockDim.x + threadIdx.x) >> 5;
    if (warp_global >= n_nodes) return;
    const int lane = threadIdx.x & 31;
    const int n = warp_global;

    const float keep = *keep_rate_p;          // tiny, cached fine

    const float s    = __ldcs(&interact[(size_t)n * M_MB + lane]);
    const float init = __ldcs(&initial [(size_t)n * M_MB + lane]);

    // ---- top-K via K iterative warp argmax (tie -> lower index) ----
    float v = s;
    int   my_sel = 0;
    bool  picked = false;
    #pragma unroll
    for (int k = 0; k < K_TOP; ++k) {
        float mv = v;
        int   mi = lane;
        #pragma unroll
        for (int off = 16; off > 0; off >>= 1) {
            float ov = __shfl_xor_sync(0xffffffffu, mv, off);
            int   oi = __shfl_xor_sync(0xffffffffu, mi, off);
            if (ov > mv || (ov == mv && oi < mi)) { mv = ov; mi = oi; }
        }
        if (lane == k)  my_sel = mi;
        if (lane == mi) { v = -CUDART_INF_F; picked = true; }
    }

    // ---- selected ids: store early, streaming ----
    if (lane < K_TOP) {
        const int id = __ldcs(&source_id[(size_t)n * M_MB + my_sel]);
        __stcs(&out_ids[(size_t)n * K_TOP + lane], (float)id);  // exact: id < 2^24
    }

    // ---- pseudo-adjacency (non-topk sigmoid term == 0 in fp32) ----
    const float sig = picked ? (1.0f / (1.0f + expf(-s))) : 0.0f;
    const float adj = (1.0f - keep) * sig + keep * init;

    // coefficient = sum(adj) + 1
    float c = adj;
    #pragma unroll
    for (int off = 16; off > 0; off >>= 1)
        c += __shfl_xor_sync(0xffffffffu, c, off);
    const float inv_c = 1.0f / (c + 1.0f);

    // ---- weighted neighbor reduction: acc[d] = sum_m adj[m]*src[n,m,d] ----
    const float4* __restrict__ src4 =
        reinterpret_cast<const float4*>(src_info + (size_t)n * M_MB * D_FEAT);

    float4 acc = make_float4(0.f, 0.f, 0.f, 0.f);
    #pragma unroll
    for (int m = 0; m < M_MB; ++m) {
        const float  a = __shfl_sync(0xffffffffu, adj, m);
        const float4 x = __ldcs(&src4[m * (D_FEAT / 4) + lane]);  // evict-first
        acc.x = fmaf(a, x.x, acc.x);
        acc.y = fmaf(a, x.y, acc.y);
        acc.z = fmaf(a, x.z, acc.z);
        acc.w = fmaf(a, x.w, acc.w);
    }

    const float4 b =
        __ldcs(&reinterpret_cast<const float4*>(buffer + (size_t)n * D_FEAT)[lane]);
    acc.x = (acc.x + b.x) * inv_c;
    acc.y = (acc.y + b.y) * inv_c;
    acc.z = (acc.z + b.z) * inv_c;
    acc.w = (acc.w + b.w) * inv_c;

    __stcs(&reinterpret_cast<float4*>(out_agg + (size_t)n * D_FEAT)[lane], acc);
}

extern "C" void kernel_launch(void* const* d_in, const int* in_sizes, int n_in,
                              void* d_out, int out_size)
{
    const float* interact = (const float*)d_in[0];
    const float* initial  = (const float*)d_in[1];
    const float* src_info = (const float*)d_in[2];
    const float* buffer   = (const float*)d_in[3];
    const float* keep     = (const float*)d_in[5];
    const int*   sid      = (const int*)d_in[6];

    const int n_nodes = in_sizes[0] / M_MB;   // 50000

    float* out_agg = (float*)d_out;
    float* out_ids = out_agg + (size_t)n_nodes * D_FEAT;

    const int warps_per_block = 8;            // 256 threads
    const int blocks = (n_nodes + warps_per_block - 1) / warps_per_block;
    gcn_kernel<<<blocks, warps_per_block * 32>>>(
        interact, initial, src_info, buffer, keep, sid,
        out_agg, out_ids, n_nodes);
}

// round 9
// speedup vs baseline: 1.0358x; 1.0358x over previous
#include <cuda_runtime.h>
#include <math_constants.h>

// GCN_20753281975108: top-k masked neighbor aggregation.
// N=50000 nodes, M=32 mailbox, D=128 features, K=8 top-k.
// Output (f32): [ aggregate: N*D ][ selected_ids: N*K cast to f32 ]
//
// Best-measured config (R7, 125.9us): one node per warp, regs 32,
// occ ~90%, grid 6250. Streaming cache policy ONLY where it pays:
// __ldcs on the 819 MB src_info stream + __stcs on outputs. Small
// latency-critical loads (scores, ids, buffer) keep default caching —
// R8 showed evict-first on those is net-negative.

#define M_MB   32
#define D_FEAT 128
#define K_TOP  8

__global__ __launch_bounds__(256, 8)
void gcn_kernel(const float* __restrict__ interact,
                const float* __restrict__ initial,
                const float* __restrict__ src_info,
                const float* __restrict__ buffer,
                const float* __restrict__ keep_rate_p,
                const int* __restrict__ source_id,
                float* __restrict__ out_agg,
                float* __restrict__ out_ids,
                int n_nodes)
{
    const int warp_global = (blockIdx.x * blockDim.x + threadIdx.x) >> 5;
    if (warp_global >= n_nodes) return;
    const int lane = threadIdx.x & 31;
    const int n = warp_global;

    const float keep = *keep_rate_p;

    const float s    = interact[(size_t)n * M_MB + lane];
    const float init = initial [(size_t)n * M_MB + lane];

    // ---- top-K via K iterative warp argmax (tie -> lower index) ----
    float v = s;
    int   my_sel = 0;
    bool  picked = false;
    #pragma unroll
    for (int k = 0; k < K_TOP; ++k) {
        float mv = v;
        int   mi = lane;
        #pragma unroll
        for (int off = 16; off > 0; off >>= 1) {
            float ov = __shfl_xor_sync(0xffffffffu, mv, off);
            int   oi = __shfl_xor_sync(0xffffffffu, mi, off);
            if (ov > mv || (ov == mv && oi < mi)) { mv = ov; mi = oi; }
        }
        if (lane == k)  my_sel = mi;
        if (lane == mi) { v = -CUDART_INF_F; picked = true; }
    }

    // ---- selected ids: store early, streaming store ----
    if (lane < K_TOP) {
        const int id = source_id[(size_t)n * M_MB + my_sel];
        __stcs(&out_ids[(size_t)n * K_TOP + lane], (float)id);  // exact: id < 2^24
    }

    // ---- pseudo-adjacency (non-topk sigmoid term == 0 in fp32) ----
    const float sig = picked ? (1.0f / (1.0f + expf(-s))) : 0.0f;
    const float adj = (1.0f - keep) * sig + keep * init;

    // coefficient = sum(adj) + 1
    float c = adj;
    #pragma unroll
    for (int off = 16; off > 0; off >>= 1)
        c += __shfl_xor_sync(0xffffffffu, c, off);
    const float inv_c = 1.0f / (c + 1.0f);

    // ---- weighted neighbor reduction: acc[d] = sum_m adj[m]*src[n,m,d] ----
    const float4* __restrict__ src4 =
        reinterpret_cast<const float4*>(src_info + (size_t)n * M_MB * D_FEAT);

    float4 acc = make_float4(0.f, 0.f, 0.f, 0.f);
    #pragma unroll
    for (int m = 0; m < M_MB; ++m) {
        const float  a = __shfl_sync(0xffffffffu, adj, m);
        const float4 x = __ldcs(&src4[m * (D_FEAT / 4) + lane]);  // evict-first
        acc.x = fmaf(a, x.x, acc.x);
        acc.y = fmaf(a, x.y, acc.y);
        acc.z = fmaf(a, x.z, acc.z);
        acc.w = fmaf(a, x.w, acc.w);
    }

    const float4 b =
        reinterpret_cast<const float4*>(buffer + (size_t)n * D_FEAT)[lane];
    acc.x = (acc.x + b.x) * inv_c;
    acc.y = (acc.y + b.y) * inv_c;
    acc.z = (acc.z + b.z) * inv_c;
    acc.w = (acc.w + b.w) * inv_c;

    __stcs(&reinterpret_cast<float4*>(out_agg + (size_t)n * D_FEAT)[lane], acc);
}

extern "C" void kernel_launch(void* const* d_in, const int* in_sizes, int n_in,
                              void* d_out, int out_size)
{
    const float* interact = (const float*)d_in[0];
    const float* initial  = (const float*)d_in[1];
    const float* src_info = (const float*)d_in[2];
    const float* buffer   = (const float*)d_in[3];
    const float* keep     = (const float*)d_in[5];
    const int*   sid      = (const int*)d_in[6];

    const int n_nodes = in_sizes[0] / M_MB;   // 50000

    float* out_agg = (float*)d_out;
    float* out_ids = out_agg + (size_t)n_nodes * D_FEAT;

    const int warps_per_block = 8;            // 256 threads
    const int blocks = (n_nodes + warps_per_block - 1) / warps_per_block;
    gcn_kernel<<<blocks, warps_per_block * 32>>>(
        interact, initial, src_info, buffer, keep, sid,
        out_agg, out_ids, n_nodes);
}

// round 10
// speedup vs baseline: 1.0468x; 1.0107x over previous
#include <cuda_runtime.h>
#include <math_constants.h>

// GCN_20753281975108: top-k masked neighbor aggregation.
// N=50000 nodes, M=32 mailbox, D=128 features, K=8 top-k.
// Output (f32): [ aggregate: N*D ][ selected_ids: N*K cast to f32 ]
//
// Plateau config (R7/R9: ~126us, DRAM 85%): one node per warp, regs 32.
// Final micro-tuning: __ldlu (last-use) on the read-once 819 MB
// src_info stream, __stcs on outputs, 512-thread blocks (same 64-warp
// occupancy, half the CTA scheduling events).

#define M_MB   32
#define D_FEAT 128
#define K_TOP  8

__global__ __launch_bounds__(512, 4)
void gcn_kernel(const float* __restrict__ interact,
                const float* __restrict__ initial,
                const float* __restrict__ src_info,
                const float* __restrict__ buffer,
                const float* __restrict__ keep_rate_p,
                const int* __restrict__ source_id,
                float* __restrict__ out_agg,
                float* __restrict__ out_ids,
                int n_nodes)
{
    const int warp_global = (blockIdx.x * blockDim.x + threadIdx.x) >> 5;
    if (warp_global >= n_nodes) return;
    const int lane = threadIdx.x & 31;
    const int n = warp_global;

    const float keep = *keep_rate_p;

    const float s    = interact[(size_t)n * M_MB + lane];
    const float init = initial [(size_t)n * M_MB + lane];

    // ---- top-K via K iterative warp argmax (tie -> lower index) ----
    float v = s;
    int   my_sel = 0;
    bool  picked = false;
    #pragma unroll
    for (int k = 0; k < K_TOP; ++k) {
        float mv = v;
        int   mi = lane;
        #pragma unroll
        for (int off = 16; off > 0; off >>= 1) {
            float ov = __shfl_xor_sync(0xffffffffu, mv, off);
            int   oi = __shfl_xor_sync(0xffffffffu, mi, off);
            if (ov > mv || (ov == mv && oi < mi)) { mv = ov; mi = oi; }
        }
        if (lane == k)  my_sel = mi;
        if (lane == mi) { v = -CUDART_INF_F; picked = true; }
    }

    // ---- selected ids: store early, streaming store ----
    if (lane < K_TOP) {
        const int id = source_id[(size_t)n * M_MB + my_sel];
        __stcs(&out_ids[(size_t)n * K_TOP + lane], (float)id);  // exact: id < 2^24
    }

    // ---- pseudo-adjacency (non-topk sigmoid term == 0 in fp32) ----
    const float sig = picked ? (1.0f / (1.0f + expf(-s))) : 0.0f;
    const float adj = (1.0f - keep) * sig + keep * init;

    // coefficient = sum(adj) + 1
    float c = adj;
    #pragma unroll
    for (int off = 16; off > 0; off >>= 1)
        c += __shfl_xor_sync(0xffffffffu, c, off);
    const float inv_c = 1.0f / (c + 1.0f);

    // ---- weighted neighbor reduction: acc[d] = sum_m adj[m]*src[n,m,d] ----
    const float4* __restrict__ src4 =
        reinterpret_cast<const float4*>(src_info + (size_t)n * M_MB * D_FEAT);

    float4 acc = make_float4(0.f, 0.f, 0.f, 0.f);
    #pragma unroll
    for (int m = 0; m < M_MB; ++m) {
        const float  a = __shfl_sync(0xffffffffu, adj, m);
        const float4 x = __ldlu(&src4[m * (D_FEAT / 4) + lane]);  // last-use
        acc.x = fmaf(a, x.x, acc.x);
        acc.y = fmaf(a, x.y, acc.y);
        acc.z = fmaf(a, x.z, acc.z);
        acc.w = fmaf(a, x.w, acc.w);
    }

    const float4 b =
        reinterpret_cast<const float4*>(buffer + (size_t)n * D_FEAT)[lane];
    acc.x = (acc.x + b.x) * inv_c;
    acc.y = (acc.y + b.y) * inv_c;
    acc.z = (acc.z + b.z) * inv_c;
    acc.w = (acc.w + b.w) * inv_c;

    __stcs(&reinterpret_cast<float4*>(out_agg + (size_t)n * D_FEAT)[lane], acc);
}

extern "C" void kernel_launch(void* const* d_in, const int* in_sizes, int n_in,
                              void* d_out, int out_size)
{
    const float* interact = (const float*)d_in[0];
    const float* initial  = (const float*)d_in[1];
    const float* src_info = (const float*)d_in[2];
    const float* buffer   = (const float*)d_in[3];
    const float* keep     = (const float*)d_in[5];
    const int*   sid      = (const int*)d_in[6];

    const int n_nodes = in_sizes[0] / M_MB;   // 50000

    float* out_agg = (float*)d_out;
    float* out_ids = out_agg + (size_t)n_nodes * D_FEAT;

    const int warps_per_block = 16;           // 512 threads
    const int blocks = (n_nodes + warps_per_block - 1) / warps_per_block;
    gcn_kernel<<<blocks, warps_per_block * 32>>>(
        interact, initial, src_info, buffer, keep, sid,
        out_agg, out_ids, n_nodes);
}

// round 11
// speedup vs baseline: 1.0492x; 1.0023x over previous
#include <cuda_runtime.h>
#include <math_constants.h>

// GCN_20753281975108: top-k masked neighbor aggregation.
// N=50000 nodes, M=32 mailbox, D=128 features, K=8 top-k.
// Output (f32): [ aggregate: N*D ][ selected_ids: N*K cast to f32 ]
//
// Terminal config: one node per warp, regs 32, 256-thread blocks
// (best ncu DRAM% of the plateau), __ldlu last-use on the read-once
// 819 MB src_info stream, __stcs on outputs. Everything else default
// caching (R8 showed hints on small latency-critical loads regress).
// Kernel is at the HBM wall: ~891 MB irreducible / ~6.8 TB/s.

#define M_MB   32
#define D_FEAT 128
#define K_TOP  8

__global__ __launch_bounds__(256, 8)
void gcn_kernel(const float* __restrict__ interact,
                const float* __restrict__ initial,
                const float* __restrict__ src_info,
                const float* __restrict__ buffer,
                const float* __restrict__ keep_rate_p,
                const int* __restrict__ source_id,
                float* __restrict__ out_agg,
                float* __restrict__ out_ids,
                int n_nodes)
{
    const int warp_global = (blockIdx.x * blockDim.x + threadIdx.x) >> 5;
    if (warp_global >= n_nodes) return;
    const int lane = threadIdx.x & 31;
    const int n = warp_global;

    const float keep = *keep_rate_p;

    const float s    = interact[(size_t)n * M_MB + lane];
    const float init = initial [(size_t)n * M_MB + lane];

    // ---- top-K via K iterative warp argmax (tie -> lower index) ----
    float v = s;
    int   my_sel = 0;
    bool  picked = false;
    #pragma unroll
    for (int k = 0; k < K_TOP; ++k) {
        float mv = v;
        int   mi = lane;
        #pragma unroll
        for (int off = 16; off > 0; off >>= 1) {
            float ov = __shfl_xor_sync(0xffffffffu, mv, off);
            int   oi = __shfl_xor_sync(0xffffffffu, mi, off);
            if (ov > mv || (ov == mv && oi < mi)) { mv = ov; mi = oi; }
        }
        if (lane == k)  my_sel = mi;
        if (lane == mi) { v = -CUDART_INF_F; picked = true; }
    }

    // ---- selected ids: store early, streaming store ----
    if (lane < K_TOP) {
        const int id = source_id[(size_t)n * M_MB + my_sel];
        __stcs(&out_ids[(size_t)n * K_TOP + lane], (float)id);  // exact: id < 2^24
    }

    // ---- pseudo-adjacency (non-topk sigmoid term == 0 in fp32) ----
    const float sig = picked ? (1.0f / (1.0f + expf(-s))) : 0.0f;
    const float adj = (1.0f - keep) * sig + keep * init;

    // coefficient = sum(adj) + 1
    float c = adj;
    #pragma unroll
    for (int off = 16; off > 0; off >>= 1)
        c += __shfl_xor_sync(0xffffffffu, c, off);
    const float inv_c = 1.0f / (c + 1.0f);

    // ---- weighted neighbor reduction: acc[d] = sum_m adj[m]*src[n,m,d] ----
    const float4* __restrict__ src4 =
        reinterpret_cast<const float4*>(src_info + (size_t)n * M_MB * D_FEAT);

    float4 acc = make_float4(0.f, 0.f, 0.f, 0.f);
    #pragma unroll
    for (int m = 0; m < M_MB; ++m) {
        const float  a = __shfl_sync(0xffffffffu, adj, m);
        const float4 x = __ldlu(&src4[m * (D_FEAT / 4) + lane]);  // last-use
        acc.x = fmaf(a, x.x, acc.x);
        acc.y = fmaf(a, x.y, acc.y);
        acc.z = fmaf(a, x.z, acc.z);
        acc.w = fmaf(a, x.w, acc.w);
    }

    const float4 b =
        reinterpret_cast<const float4*>(buffer + (size_t)n * D_FEAT)[lane];
    acc.x = (acc.x + b.x) * inv_c;
    acc.y = (acc.y + b.y) * inv_c;
    acc.z = (acc.z + b.z) * inv_c;
    acc.w = (acc.w + b.w) * inv_c;

    __stcs(&reinterpret_cast<float4*>(out_agg + (size_t)n * D_FEAT)[lane], acc);
}

extern "C" void kernel_launch(void* const* d_in, const int* in_sizes, int n_in,
                              void* d_out, int out_size)
{
    const float* interact = (const float*)d_in[0];
    const float* initial  = (const float*)d_in[1];
    const float* src_info = (const float*)d_in[2];
    const float* buffer   = (const float*)d_in[3];
    const float* keep     = (const float*)d_in[5];
    const int*   sid      = (const int*)d_in[6];

    const int n_nodes = in_sizes[0] / M_MB;   // 50000

    float* out_agg = (float*)d_out;
    float* out_ids = out_agg + (size_t)n_nodes * D_FEAT;

    const int warps_per_block = 8;            // 256 threads
    const int blocks = (n_nodes + warps_per_block - 1) / warps_per_block;
    gcn_kernel<<<blocks, warps_per_block * 32>>>(
        interact, initial, src_info, buffer, keep, sid,
        out_agg, out_ids, n_nodes);
}